// round 4
// baseline (speedup 1.0000x reference)
#include <cuda_runtime.h>
#include <math.h>

#define B   8
#define C   128
#define HWD 128
#define L   41
#define CI  256
#define PLANE (HWD*HWD)

// ---------------- device scratch (no cudaMalloc allowed) ----------------
__device__ float g_fuse[(size_t)B*C*PLANE];   // 67 MB conv output
__device__ float g_sum_d[B*L*C];
__device__ float g_sum_f[B*L*C];
__device__ int   g_cnt[B*L];
__device__ float g_gd[B*C];
__device__ float g_gf[B*C];

// ---------------- f32x2 packed-FMA helpers (B300) ----------------
__device__ __forceinline__ unsigned long long pack2(float a, float b){
    unsigned long long r;
    asm("mov.b64 %0, {%1,%2};" : "=l"(r) : "f"(a), "f"(b));
    return r;
}
__device__ __forceinline__ void fma2(unsigned long long &d,
                                     unsigned long long a, unsigned long long b){
    asm("fma.rn.f32x2 %0, %1, %2, %0;" : "+l"(d) : "l"(a), "l"(b));
}
__device__ __forceinline__ void unpack2(unsigned long long v, float &lo, float &hi){
    asm("mov.b64 {%0,%1}, %2;" : "=f"(lo), "=f"(hi) : "l"(v));
}
__device__ __forceinline__ float sigmoidf(float x){
    return 1.0f / (1.0f + __expf(-x));
}

// ---------------- zero scratch (runs every replay) ----------------
__global__ void k_zero(){
    int i = blockIdx.x*256 + threadIdx.x;
    if (i < B*L*C){ g_sum_d[i] = 0.f; g_sum_f[i] = 0.f; }
    if (i < B*L)    g_cnt[i] = 0;
}

// ---------------- segment reduction (no hot-loop atomics) ----------------
// grid (8 row-tiles, B), block 256. which: 0 = d pass (+counts), 1 = fuse pass.
__global__ void k_seg(const float* __restrict__ feats_d,
                      const int*   __restrict__ label,
                      int which){
    __shared__ float ssum[2][L*C];          // 42 KB
    __shared__ unsigned char slab[2048];    // labels < 41
    __shared__ int scnt[L];
    int b    = blockIdx.y;
    int tile = blockIdx.x;
    int tid  = threadIdx.x;
    int c = tid & 127, h = tid >> 7;

    for (int i = tid; i < 2*L*C; i += 256) ((float*)ssum)[i] = 0.f;
    if (tid < L) scnt[tid] = 0;
    __syncthreads();

    int y0 = tile * 16;
    const int* lb = label + (size_t)b * 512 * 512;
    for (int p = tid; p < 2048; p += 256){
        int y = y0 + (p >> 7);
        int x = p & 127;
        int lv = lb[(y << 2) * 512 + (x << 2)];   // nearest resize: idx*4
        slab[p] = (unsigned char)lv;
        if (which == 0) atomicAdd(&scnt[lv], 1);
    }
    __syncthreads();

    const float* src = (which == 0) ? feats_d : g_fuse;
    const float* f = src + ((size_t)b*C + c) * PLANE + (size_t)y0 * HWD;
    float* sm = ssum[h];
    int pbase = h * 1024;
    #pragma unroll 4
    for (int i = 0; i < 1024; i += 4){
        int p = pbase + i;
        float4 v = *(const float4*)(f + p);
        sm[slab[p+0]*C + c] += v.x;
        sm[slab[p+1]*C + c] += v.y;
        sm[slab[p+2]*C + c] += v.z;
        sm[slab[p+3]*C + c] += v.w;
    }
    __syncthreads();

    float* sums = (which == 0) ? g_sum_d : g_sum_f;
    for (int i = tid; i < L*C; i += 256)
        atomicAdd(&sums[b*L*C + i], ssum[0][i] + ssum[1][i]);
    if (which == 0 && tid < L) atomicAdd(&g_cnt[b*L + tid], scnt[tid]);
}

// ---------------- gate: mean -> class L2-norm -> sum -> 2x 1x1 conv ----------------
// grid B, block 128 (thread = channel)
__global__ void k_gate(int which,
                       const float* __restrict__ base,
                       const float* __restrict__ w1,   // [8, C]
                       const float* __restrict__ w2){  // [C, 8]
    int b = blockIdx.x;
    int c = threadIdx.x;
    __shared__ float s_s[C];
    __shared__ float s_h[8];
    const float* sums = (which == 0) ? g_sum_d : g_sum_f;

    float sm = 0.f, n2 = 0.f;
    for (int l = 0; l < L; l++){
        int   cnt = g_cnt[b*L + l];
        float m;
        if (cnt > 0) m = sums[(b*L + l)*C + c] / (float)cnt;
        else         m = base[(b*L + l)*C + c];
        sm += m;
        n2 += m * m;
    }
    // att/=max(norm,eps); s = sum over classes  ==  sm / max(sqrt(n2), eps)
    s_s[c] = sm / fmaxf(sqrtf(n2), 1e-12f);
    __syncthreads();
    if (c < 8){
        float a = 0.f;
        for (int k = 0; k < C; k++) a += s_s[k] * w1[c*C + k];
        s_h[c] = fmaxf(a, 0.f);
    }
    __syncthreads();
    float a = 0.f;
    #pragma unroll
    for (int o = 0; o < 8; o++) a += s_h[o] * w2[c*8 + o];
    float g = sigmoidf(a);
    if (which == 0) g_gd[b*C + c] = g;
    else            g_gf[b*C + c] = g;
}

// ---------------- 3x3 conv (implicit concat, fp32 with packed f32x2 FMA) --------
// block: 16 out-ch x (8 rows x 128 cols); thread: 4 px x 16 co; grid (16, 8, B)
#define CO_T 16
#define CCH  8
__global__ __launch_bounds__(256, 2)
void k_conv(const float* __restrict__ r,
            const float* __restrict__ d,
            const float* __restrict__ w){
    __shared__ float xs[CCH][10][132];      // 42240 B
    __shared__ float ws[CCH*9*CO_T];        //  4608 B
    int tid  = threadIdx.x;
    int y0   = blockIdx.x * 8;
    int co0  = blockIdx.y * CO_T;
    int b    = blockIdx.z;
    int py   = tid >> 5;
    int px0  = (tid & 31) << 2;

    unsigned long long acc[4][8];
    #pragma unroll
    for (int p = 0; p < 4; p++)
        #pragma unroll
        for (int j = 0; j < 8; j++) acc[p][j] = 0ull;

    const float* rb = r + (size_t)b*C*PLANE;
    const float* db = d + (size_t)b*C*PLANE;

    for (int cc0 = 0; cc0 < CI; cc0 += CCH){
        __syncthreads();
        // weights chunk: [ci][k][co], 1152 elems
        for (int idx = tid; idx < CCH*9*CO_T; idx += 256){
            int co = idx & 15;
            int k  = (idx >> 4) % 9;
            int ci = idx / (16*9);
            ws[(ci*9 + k)*CO_T + co] = w[((size_t)(co0+co)*CI + cc0 + ci)*9 + k];
        }
        // input tile with halo: 8 x 10 x 130 elems; concat computed on the fly
        for (int idx = tid; idx < CCH*10*130; idx += 256){
            int ix = idx % 130;
            int iy = (idx / 130) % 10;
            int ci = idx / 1300;
            int gy = y0 + iy - 1;
            int gx = ix - 1;
            float v = 0.f;
            if ((unsigned)gy < 128u && (unsigned)gx < 128u){
                int cin = cc0 + ci;
                if (cin < C){
                    size_t o = (size_t)cin*PLANE + gy*HWD + gx;
                    v = rb[o] + db[o];
                } else {
                    size_t o = (size_t)(cin - C)*PLANE + gy*HWD + gx;
                    v = rb[o] * sigmoidf(db[o]);
                }
            }
            xs[ci][iy][ix] = v;
        }
        __syncthreads();

        #pragma unroll 2
        for (int ci = 0; ci < CCH; ci++){
            #pragma unroll
            for (int ky = 0; ky < 3; ky++){
                const float* xrow = &xs[ci][py + ky][px0];
                float xv[6];
                #pragma unroll
                for (int t = 0; t < 6; t++) xv[t] = xrow[t];
                #pragma unroll
                for (int kx = 0; kx < 3; kx++){
                    const unsigned long long* wp =
                        (const unsigned long long*)&ws[(ci*9 + ky*3 + kx)*CO_T];
                    unsigned long long w2[8];
                    #pragma unroll
                    for (int j = 0; j < 8; j++) w2[j] = wp[j];
                    #pragma unroll
                    for (int p = 0; p < 4; p++){
                        unsigned long long xx = pack2(xv[kx + p], xv[kx + p]);
                        #pragma unroll
                        for (int j = 0; j < 8; j++) fma2(acc[p][j], w2[j], xx);
                    }
                }
            }
        }
    }

    // store: per j, gather 4 consecutive px into float4 (coalesced)
    int y = y0 + py;
    float* ob = g_fuse + (size_t)b*C*PLANE + (size_t)y*HWD + px0;
    #pragma unroll
    for (int j = 0; j < 8; j++){
        float lo[4], hi[4];
        #pragma unroll
        for (int p = 0; p < 4; p++) unpack2(acc[p][j], lo[p], hi[p]);
        float4 v0 = make_float4(lo[0], lo[1], lo[2], lo[3]);
        float4 v1 = make_float4(hi[0], hi[1], hi[2], hi[3]);
        *(float4*)(ob + (size_t)(co0 + 2*j    )*PLANE) = v0;
        *(float4*)(ob + (size_t)(co0 + 2*j + 1)*PLANE) = v1;
    }
}

// ---------------- final gated sum ----------------
__global__ void k_final(const float* __restrict__ dten, float* __restrict__ out){
    size_t i = (size_t)blockIdx.x*256 + threadIdx.x;   // float4 index
    size_t e = i * 4;
    int bc = (int)(e >> 14);        // [b][c] plane index (plane = 16384)
    float gf = g_gf[bc];
    float gd = g_gd[bc];
    float4 f4 = *(const float4*)(g_fuse + e);
    float4 d4 = *(const float4*)(dten + e);
    float4 o;
    o.x = f4.x*gf + d4.x*gd;
    o.y = f4.y*gf + d4.y*gd;
    o.z = f4.z*gf + d4.z*gd;
    o.w = f4.w*gf + d4.w*gd;
    *(float4*)(out + e) = o;
}

// ---------------- launch ----------------
extern "C" void kernel_launch(void* const* d_in, const int* in_sizes, int n_in,
                              void* d_out, int out_size){
    const float* r      = (const float*)d_in[0];
    const float* d      = (const float*)d_in[1];
    const int*   label  = (const int*)  d_in[2];
    const float* conv_w = (const float*)d_in[3];
    const float* f_w1   = (const float*)d_in[4];
    const float* f_w2   = (const float*)d_in[5];
    const float* d_w1   = (const float*)d_in[6];
    const float* d_w2   = (const float*)d_in[7];
    const float* base_f = (const float*)d_in[8];
    const float* base_d = (const float*)d_in[9];
    float* out = (float*)d_out;

    k_zero<<<(B*L*C + 255)/256, 256>>>();

    dim3 segGrid(8, B);
    k_seg<<<segGrid, 256>>>(d, label, 0);            // d-pass (+counts)
    k_gate<<<B, 128>>>(0, base_d, d_w1, d_w2);       // -> g_gd

    dim3 convGrid(16, 8, B);
    k_conv<<<convGrid, 256>>>(r, d, conv_w);         // -> g_fuse

    k_seg<<<segGrid, 256>>>(d, label, 1);            // fuse-pass (reads g_fuse)
    k_gate<<<B, 128>>>(1, base_f, f_w1, f_w2);       // -> g_gf

    k_final<<<(B*C*PLANE/4 + 255)/256, 256>>>(d, out);
}

// round 11
// speedup vs baseline: 3.2754x; 3.2754x over previous
#include <cuda_runtime.h>
#include <cuda_fp16.h>
#include <math.h>
#include <stdint.h>

#define B   8
#define C   128
#define HWD 128
#define L   41
#define CI  256
#define PLANE (HWD*HWD)

// ---------------- device scratch (no cudaMalloc allowed) ----------------
__device__ float g_fuse[(size_t)B*C*PLANE];            // conv out [b][co][y][x]
__device__ float g_sum_d[B*L*C];
__device__ float g_sum_f[B*L*C];
__device__ int   g_cnt[B*L];
__device__ float g_gd[B*C];
__device__ float g_gf[B*C];
__device__ unsigned short g_xh[(size_t)B*PLANE*CI];    // [b][y][x][ci] fp16 hi
__device__ unsigned short g_xl[(size_t)B*PLANE*CI];    // fp16 lo (residual)
__device__ unsigned short g_w [9*C*CI];                // [tap][co][ci] fp16

// ---------------- helpers ----------------
__device__ __forceinline__ float sigmoidf(float x){
    return 1.0f / (1.0f + __expf(-x));
}
__device__ __forceinline__ uint32_t smem_u32(const void* p){
    uint32_t a;
    asm("{ .reg .u64 t; cvta.to.shared.u64 t, %1; cvt.u32.u64 %0, t; }"
        : "=r"(a) : "l"(p));
    return a;
}
__device__ __forceinline__ void ldm_x4(uint32_t &r0, uint32_t &r1,
                                       uint32_t &r2, uint32_t &r3, uint32_t a){
    asm volatile("ldmatrix.sync.aligned.m8n8.x4.shared.b16 {%0,%1,%2,%3}, [%4];"
                 : "=r"(r0), "=r"(r1), "=r"(r2), "=r"(r3) : "r"(a));
}
__device__ __forceinline__ void ldm_x2(uint32_t &r0, uint32_t &r1, uint32_t a){
    asm volatile("ldmatrix.sync.aligned.m8n8.x2.shared.b16 {%0,%1}, [%2];"
                 : "=r"(r0), "=r"(r1) : "r"(a));
}
__device__ __forceinline__ void mma16816(float* c, const uint32_t* a, const uint32_t* b){
    asm volatile("mma.sync.aligned.m16n8k16.row.col.f32.f16.f16.f32 "
        "{%0,%1,%2,%3}, {%4,%5,%6,%7}, {%8,%9}, {%0,%1,%2,%3};"
        : "+f"(c[0]), "+f"(c[1]), "+f"(c[2]), "+f"(c[3])
        : "r"(a[0]), "r"(a[1]), "r"(a[2]), "r"(a[3]), "r"(b[0]), "r"(b[1]));
}
__device__ __forceinline__ void cpasync16(uint32_t saddr, const void* g, int ok){
    asm volatile("cp.async.cg.shared.global [%0], [%1], 16, %2;"
                 :: "r"(saddr), "l"(g), "r"(ok ? 16 : 0) : "memory");
}
#define CP_COMMIT() asm volatile("cp.async.commit_group;" ::: "memory")

// ---------------- zero scratch (runs every replay) ----------------
__global__ void k_zero(){
    int i = blockIdx.x*256 + threadIdx.x;
    if (i < B*L*C){ g_sum_d[i] = 0.f; g_sum_f[i] = 0.f; }
    if (i < B*L)    g_cnt[i] = 0;
}

// ---------------- weight prep: fp32 -> fp16, [tap][co][ci] ----------------
__global__ void kprep_w(const float* __restrict__ w){
    int tap = blockIdx.x;      // ky*3+kx
    int co  = blockIdx.y;
    int ci  = threadIdx.x;     // 256
    float v = w[((size_t)co*CI + ci)*9 + tap];
    __half h = __float2half(v);
    g_w[(tap*C + co)*CI + ci] = *(unsigned short*)&h;
}

// ---------------- x prep: add/mul, fp16 split, transpose to [b][y][x][ci] ------
#define XP_PITCH 130
__global__ void kprep_x(const float* __restrict__ r, const float* __restrict__ d){
    extern __shared__ unsigned short ps[];               // sxh[256][130], sxl[...]
    unsigned short* sxh = ps;
    unsigned short* sxl = ps + CI*XP_PITCH;
    int y = blockIdx.x, b = blockIdx.y;
    int tid = threadIdx.x;
    int x = tid & 127, chalf = tid >> 7;

    for (int cc = 0; cc < 64; cc++){
        int ci = cc*2 + chalf;
        size_t idx = ((size_t)(b*C + ci))*PLANE + y*HWD + x;
        float rv = r[idx], dv = d[idx];
        float va = rv + dv;
        float vm = rv * sigmoidf(dv);
        __half ah = __float2half(va);
        __half al = __float2half(va - __half2float(ah));
        __half mh = __float2half(vm);
        __half ml = __float2half(vm - __half2float(mh));
        sxh[ci*XP_PITCH + x]         = *(unsigned short*)&ah;
        sxl[ci*XP_PITCH + x]         = *(unsigned short*)&al;
        sxh[(ci+128)*XP_PITCH + x]   = *(unsigned short*)&mh;
        sxl[(ci+128)*XP_PITCH + x]   = *(unsigned short*)&ml;
    }
    __syncthreads();
    // write out coalesced: [x][ci] contiguous in ci
    for (int j = tid; j < 4096; j += 256){               // uint4 units
        int xx = j >> 5, q = j & 31, c0 = q*8;
        size_t base = (((size_t)b*PLANE) + y*HWD + xx)*CI + c0;
        uint4 uh, ul;
        unsigned short th[8], tl[8];
        #pragma unroll
        for (int k = 0; k < 8; k++){
            th[k] = sxh[(c0+k)*XP_PITCH + xx];
            tl[k] = sxl[(c0+k)*XP_PITCH + xx];
        }
        uh.x = (uint32_t)th[0] | ((uint32_t)th[1] << 16);
        uh.y = (uint32_t)th[2] | ((uint32_t)th[3] << 16);
        uh.z = (uint32_t)th[4] | ((uint32_t)th[5] << 16);
        uh.w = (uint32_t)th[6] | ((uint32_t)th[7] << 16);
        ul.x = (uint32_t)tl[0] | ((uint32_t)tl[1] << 16);
        ul.y = (uint32_t)tl[2] | ((uint32_t)tl[3] << 16);
        ul.z = (uint32_t)tl[4] | ((uint32_t)tl[5] << 16);
        ul.w = (uint32_t)tl[6] | ((uint32_t)tl[7] << 16);
        *(uint4*)(g_xh + base) = uh;
        *(uint4*)(g_xl + base) = ul;
    }
}

// ---------------- HMMA conv ----------------
// CTA = one output row y, M=co(128) x N=px(128), K=64 per stage, 36 stages
// stage (48KB): W[128co][64k] | Xh[128px][64k] | Xl[128px][64k], fp16,
// rows of 128B with 16B-chunk xor swizzle: chunk_phys = q ^ (row&7).
#define STG 49152
__device__ __forceinline__ void fill_stage(uint32_t sbase, int b, int y,
                                           int it, int tid){
    int tap = it >> 2;            // 0..8
    int cic = it & 3;             // 0..3
    int dy = tap / 3, dx = tap % 3;
    int yi = y + dy - 1;
    int yok = ((unsigned)yi < 128u);
    #pragma unroll
    for (int t = 0; t < 12; t++){
        int i = tid + t*256;      // 0..3071
        int sec = i >> 10;        // 0=W, 1=Xh, 2=Xl
        int e   = i & 1023;
        int row = e >> 3, q = e & 7;
        uint32_t soff = sbase + sec*16384 + row*128 + (((uint32_t)(q ^ (row & 7))) << 4);
        const void* g;
        int ok;
        if (sec == 0){
            g = g_w + ((size_t)(tap*C + row)*CI + cic*64 + q*8);
            ok = 1;
        } else {
            int xi = row + dx - 1;
            ok = yok && ((unsigned)xi < 128u);
            int yc = ok ? yi : 0, xc = ok ? xi : 0;
            const unsigned short* src = (sec == 1) ? g_xh : g_xl;
            g = src + (((size_t)b*PLANE + yc*HWD + xc)*CI + cic*64 + q*8);
        }
        cpasync16(soff, g, ok);
    }
}

__device__ __forceinline__ void compute_stage(uint32_t sbase, int wm, int wn,
                                              int lane, float acc[4][4][4]){
    uint32_t aW  = sbase;
    uint32_t aXh = sbase + 16384;
    uint32_t aXl = sbase + 32768;
    #pragma unroll
    for (int ks = 0; ks < 4; ks++){
        uint32_t a[4][4];
        #pragma unroll
        for (int mi = 0; mi < 4; mi++){
            int row = wm*64 + mi*16 + (lane & 15);
            int ch  = ks*2 + (lane >> 4);
            ldm_x4(a[mi][0], a[mi][1], a[mi][2], a[mi][3],
                   aW + row*128 + (((uint32_t)(ch ^ (row & 7))) << 4));
        }
        uint32_t bh[4][2], bl[4][2];
        #pragma unroll
        for (int ni = 0; ni < 4; ni++){
            int row = wn*32 + ni*8 + (lane & 7);
            int ch  = ks*2 + ((lane >> 3) & 1);
            uint32_t off = row*128 + (((uint32_t)(ch ^ (row & 7))) << 4);
            ldm_x2(bh[ni][0], bh[ni][1], aXh + off);
            ldm_x2(bl[ni][0], bl[ni][1], aXl + off);
        }
        #pragma unroll
        for (int mi = 0; mi < 4; mi++)
            #pragma unroll
            for (int ni = 0; ni < 4; ni++){
                mma16816(acc[mi][ni], a[mi], bh[ni]);
                mma16816(acc[mi][ni], a[mi], bl[ni]);
            }
    }
}

__global__ __launch_bounds__(256, 2)
void k_conv_mma(){
    extern __shared__ char dsm[];
    uint32_t sb0 = smem_u32(dsm);
    sb0 = (sb0 + 127u) & ~127u;

    int tid = threadIdx.x, lane = tid & 31, wid = tid >> 5;
    int wm = wid & 1, wn = wid >> 1;      // 2(M) x 4(N)
    int y = blockIdx.x, b = blockIdx.y;

    float acc[4][4][4];
    #pragma unroll
    for (int mi = 0; mi < 4; mi++)
        #pragma unroll
        for (int ni = 0; ni < 4; ni++)
            #pragma unroll
            for (int k = 0; k < 4; k++) acc[mi][ni][k] = 0.f;

    fill_stage(sb0, b, y, 0, tid);
    CP_COMMIT();

    for (int it = 0; it < 36; it++){
        int s = it & 1;
        if (it < 35){
            fill_stage(sb0 + ((it + 1) & 1)*STG, b, y, it + 1, tid);
            CP_COMMIT();
            asm volatile("cp.async.wait_group 1;" ::: "memory");
        } else {
            asm volatile("cp.async.wait_group 0;" ::: "memory");
        }
        __syncthreads();
        compute_stage(sb0 + s*STG, wm, wn, lane, acc);
        __syncthreads();
    }

    // epilogue: acc (m=co, n=px) -> g_fuse[b][co][y][px], px-contiguous float2
    int g  = lane >> 2;
    int tq = lane & 3;
    #pragma unroll
    for (int mi = 0; mi < 4; mi++){
        #pragma unroll
        for (int ni = 0; ni < 4; ni++){
            int co = wm*64 + mi*16 + g;
            int px = wn*32 + ni*8 + tq*2;
            size_t o = ((size_t)(b*C + co))*PLANE + (size_t)y*HWD + px;
            float2 v0; v0.x = acc[mi][ni][0]; v0.y = acc[mi][ni][1];
            float2 v1; v1.x = acc[mi][ni][2]; v1.y = acc[mi][ni][3];
            *(float2*)(g_fuse + o)                      = v0;
            *(float2*)(g_fuse + o + (size_t)8*PLANE)    = v1;
        }
    }
}

// ---------------- segment reduction ----------------
__global__ void k_seg(const float* __restrict__ feats_d,
                      const int*   __restrict__ label,
                      int which){
    __shared__ float ssum[2][L*C];
    __shared__ unsigned char slab[2048];
    __shared__ int scnt[L];
    int b    = blockIdx.y;
    int tile = blockIdx.x;
    int tid  = threadIdx.x;
    int c = tid & 127, h = tid >> 7;

    for (int i = tid; i < 2*L*C; i += 256) ((float*)ssum)[i] = 0.f;
    if (tid < L) scnt[tid] = 0;
    __syncthreads();

    int y0 = tile * 16;
    const int* lb = label + (size_t)b * 512 * 512;
    for (int p = tid; p < 2048; p += 256){
        int y = y0 + (p >> 7);
        int x = p & 127;
        int lv = lb[(y << 2) * 512 + (x << 2)];
        slab[p] = (unsigned char)lv;
        if (which == 0) atomicAdd(&scnt[lv], 1);
    }
    __syncthreads();

    const float* src = (which == 0) ? feats_d : g_fuse;
    const float* f = src + ((size_t)b*C + c) * PLANE + (size_t)y0 * HWD;
    float* sm = ssum[h];
    int pbase = h * 1024;
    #pragma unroll 4
    for (int i = 0; i < 1024; i += 4){
        int p = pbase + i;
        float4 v = *(const float4*)(f + p);
        sm[slab[p+0]*C + c] += v.x;
        sm[slab[p+1]*C + c] += v.y;
        sm[slab[p+2]*C + c] += v.z;
        sm[slab[p+3]*C + c] += v.w;
    }
    __syncthreads();

    float* sums = (which == 0) ? g_sum_d : g_sum_f;
    for (int i = tid; i < L*C; i += 256)
        atomicAdd(&sums[b*L*C + i], ssum[0][i] + ssum[1][i]);
    if (which == 0 && tid < L) atomicAdd(&g_cnt[b*L + tid], scnt[tid]);
}

// ---------------- gate ----------------
__global__ void k_gate(int which,
                       const float* __restrict__ base,
                       const float* __restrict__ w1,
                       const float* __restrict__ w2){
    int b = blockIdx.x;
    int c = threadIdx.x;
    __shared__ float s_s[C];
    __shared__ float s_h[8];
    const float* sums = (which == 0) ? g_sum_d : g_sum_f;

    float sm = 0.f, n2 = 0.f;
    for (int l = 0; l < L; l++){
        int   cnt = g_cnt[b*L + l];
        float m;
        if (cnt > 0) m = sums[(b*L + l)*C + c] / (float)cnt;
        else         m = base[(b*L + l)*C + c];
        sm += m;
        n2 += m * m;
    }
    s_s[c] = sm / fmaxf(sqrtf(n2), 1e-12f);
    __syncthreads();
    if (c < 8){
        float a = 0.f;
        for (int k = 0; k < C; k++) a += s_s[k] * w1[c*C + k];
        s_h[c] = fmaxf(a, 0.f);
    }
    __syncthreads();
    float a = 0.f;
    #pragma unroll
    for (int o = 0; o < 8; o++) a += s_h[o] * w2[c*8 + o];
    float g = sigmoidf(a);
    if (which == 0) g_gd[b*C + c] = g;
    else            g_gf[b*C + c] = g;
}

// ---------------- final gated sum ----------------
__global__ void k_final(const float* __restrict__ dten, float* __restrict__ out){
    size_t i = (size_t)blockIdx.x*256 + threadIdx.x;
    size_t e = i * 4;
    int bc = (int)(e >> 14);
    float gf = g_gf[bc];
    float gd = g_gd[bc];
    float4 f4 = *(const float4*)(g_fuse + e);
    float4 d4 = *(const float4*)(dten + e);
    float4 o;
    o.x = f4.x*gf + d4.x*gd;
    o.y = f4.y*gf + d4.y*gd;
    o.z = f4.z*gf + d4.z*gd;
    o.w = f4.w*gf + d4.w*gd;
    *(float4*)(out + e) = o;
}

// ---------------- launch ----------------
extern "C" void kernel_launch(void* const* d_in, const int* in_sizes, int n_in,
                              void* d_out, int out_size){
    const float* r      = (const float*)d_in[0];
    const float* d      = (const float*)d_in[1];
    const int*   label  = (const int*)  d_in[2];
    const float* conv_w = (const float*)d_in[3];
    const float* f_w1   = (const float*)d_in[4];
    const float* f_w2   = (const float*)d_in[5];
    const float* d_w1   = (const float*)d_in[6];
    const float* d_w2   = (const float*)d_in[7];
    const float* base_f = (const float*)d_in[8];
    const float* base_d = (const float*)d_in[9];
    float* out = (float*)d_out;

    const int prepx_smem = 2*CI*XP_PITCH*2;
    const int conv_smem  = 2*STG + 128;
    cudaFuncSetAttribute(kprep_x, cudaFuncAttributeMaxDynamicSharedMemorySize, prepx_smem);
    cudaFuncSetAttribute(k_conv_mma, cudaFuncAttributeMaxDynamicSharedMemorySize, conv_smem);

    k_zero<<<(B*L*C + 255)/256, 256>>>();

    dim3 wgrid(9, C);
    kprep_w<<<wgrid, CI>>>(conv_w);

    dim3 xgrid(HWD, B);
    kprep_x<<<xgrid, 256, prepx_smem>>>(r, d);

    dim3 segGrid(8, B);
    k_seg<<<segGrid, 256>>>(d, label, 0);
    k_gate<<<B, 128>>>(0, base_d, d_w1, d_w2);

    dim3 convGrid(HWD, B);
    k_conv_mma<<<convGrid, 256, conv_smem>>>();

    k_seg<<<segGrid, 256>>>(d, label, 1);
    k_gate<<<B, 128>>>(1, base_f, f_w1, f_w2);

    k_final<<<(B*C*PLANE/4 + 255)/256, 256>>>(d, out);
}

// round 14
// speedup vs baseline: 5.5117x; 1.6828x over previous
#include <cuda_runtime.h>
#include <cuda_fp16.h>
#include <math.h>
#include <stdint.h>

#define B   8
#define C   128
#define HWD 128
#define L   41
#define CI  256
#define PLANE (HWD*HWD)

// ---------------- device scratch (no cudaMalloc allowed) ----------------
__device__ float g_fuse[(size_t)B*C*PLANE];            // conv out [b][co][y][x]
__device__ float g_sum_d[B*L*C];
__device__ float g_sum_f[B*L*C];
__device__ int   g_cnt[B*L];
__device__ float g_gd[B*C];
__device__ float g_gf[B*C];
__device__ unsigned short g_xh[(size_t)B*PLANE*CI];    // [b][y][x][ci] fp16
__device__ unsigned short g_w [9*C*CI];                // [tap][co][ci] fp16

// ---------------- helpers ----------------
__device__ __forceinline__ float sigmoidf(float x){
    return 1.0f / (1.0f + __expf(-x));
}
__device__ __forceinline__ uint32_t smem_u32(const void* p){
    uint32_t a;
    asm("{ .reg .u64 t; cvta.to.shared.u64 t, %1; cvt.u32.u64 %0, t; }"
        : "=r"(a) : "l"(p));
    return a;
}
__device__ __forceinline__ void ldm_x4(uint32_t &r0, uint32_t &r1,
                                       uint32_t &r2, uint32_t &r3, uint32_t a){
    asm volatile("ldmatrix.sync.aligned.m8n8.x4.shared.b16 {%0,%1,%2,%3}, [%4];"
                 : "=r"(r0), "=r"(r1), "=r"(r2), "=r"(r3) : "r"(a));
}
__device__ __forceinline__ void ldm_x2(uint32_t &r0, uint32_t &r1, uint32_t a){
    asm volatile("ldmatrix.sync.aligned.m8n8.x2.shared.b16 {%0,%1}, [%2];"
                 : "=r"(r0), "=r"(r1) : "r"(a));
}
__device__ __forceinline__ void mma16816(float* c, const uint32_t* a, const uint32_t* b){
    asm volatile("mma.sync.aligned.m16n8k16.row.col.f32.f16.f16.f32 "
        "{%0,%1,%2,%3}, {%4,%5,%6,%7}, {%8,%9}, {%0,%1,%2,%3};"
        : "+f"(c[0]), "+f"(c[1]), "+f"(c[2]), "+f"(c[3])
        : "r"(a[0]), "r"(a[1]), "r"(a[2]), "r"(a[3]), "r"(b[0]), "r"(b[1]));
}
__device__ __forceinline__ void cpasync16(uint32_t saddr, const void* g, int ok){
    asm volatile("cp.async.cg.shared.global [%0], [%1], 16, %2;"
                 :: "r"(saddr), "l"(g), "r"(ok ? 16 : 0) : "memory");
}
#define CP_COMMIT() asm volatile("cp.async.commit_group;" ::: "memory")

// ---------------- zero scratch (runs every replay) ----------------
__global__ void k_zero(){
    int i = blockIdx.x*256 + threadIdx.x;
    if (i < B*L*C){ g_sum_d[i] = 0.f; g_sum_f[i] = 0.f; }
    if (i < B*L)    g_cnt[i] = 0;
}

// ---------------- weight prep: fp32 -> fp16, [tap][co][ci] ----------------
__global__ void kprep_w(const float* __restrict__ w){
    int tap = blockIdx.x;      // ky*3+kx
    int co  = blockIdx.y;
    int ci  = threadIdx.x;     // 256
    float v = w[((size_t)co*CI + ci)*9 + tap];
    __half h = __float2half(v);
    g_w[(tap*C + co)*CI + ci] = *(unsigned short*)&h;
}

// ---------------- x prep: add/mul -> fp16, transpose to [b][y][x][ci] ------
#define XP_PITCH 136
__global__ void kprep_x(const float* __restrict__ r, const float* __restrict__ d){
    extern __shared__ unsigned short sxh[];              // [256][136]
    int y = blockIdx.x, b = blockIdx.y;
    int tid = threadIdx.x;
    int x = tid & 127, chalf = tid >> 7;

    for (int cc = 0; cc < 64; cc++){
        int ci = cc*2 + chalf;
        size_t idx = ((size_t)(b*C + ci))*PLANE + y*HWD + x;
        float rv = r[idx], dv = d[idx];
        float va = rv + dv;
        float vm = rv * sigmoidf(dv);
        __half ah = __float2half(va);
        __half mh = __float2half(vm);
        sxh[ci*XP_PITCH + x]       = *(unsigned short*)&ah;
        sxh[(ci+128)*XP_PITCH + x] = *(unsigned short*)&mh;
    }
    __syncthreads();
    // write out coalesced: [x][ci] contiguous in ci
    for (int j = tid; j < 4096; j += 256){               // uint4 units
        int xx = j >> 5, q = j & 31, c0 = q*8;
        size_t base = (((size_t)b*PLANE) + y*HWD + xx)*CI + c0;
        uint4 uh;
        unsigned short th[8];
        #pragma unroll
        for (int k = 0; k < 8; k++)
            th[k] = sxh[(c0+k)*XP_PITCH + xx];
        uh.x = (uint32_t)th[0] | ((uint32_t)th[1] << 16);
        uh.y = (uint32_t)th[2] | ((uint32_t)th[3] << 16);
        uh.z = (uint32_t)th[4] | ((uint32_t)th[5] << 16);
        uh.w = (uint32_t)th[6] | ((uint32_t)th[7] << 16);
        *(uint4*)(g_xh + base) = uh;
    }
}

// ---------------- HMMA conv ----------------
// CTA = one output row y, M=co(128) x N=px(128), K=64 per stage, 36 stages
// stage (32KB): W[128co][64k] | X[128px][64k], fp16,
// rows of 128B with 16B-chunk xor swizzle: chunk_phys = q ^ (row&7).
#define STG 32768
__device__ __forceinline__ void fill_stage(uint32_t sbase, int b, int y,
                                           int it, int tid){
    int tap = it >> 2;            // 0..8
    int cic = it & 3;             // 0..3
    int dy = tap / 3, dx = tap % 3;
    int yi = y + dy - 1;
    int yok = ((unsigned)yi < 128u);
    #pragma unroll
    for (int t = 0; t < 8; t++){
        int i = tid + t*256;      // 0..2047
        int sec = i >> 10;        // 0=W, 1=X
        int e   = i & 1023;
        int row = e >> 3, q = e & 7;
        uint32_t soff = sbase + sec*16384 + row*128 + (((uint32_t)(q ^ (row & 7))) << 4);
        const void* g;
        int ok;
        if (sec == 0){
            g = g_w + ((size_t)(tap*C + row)*CI + cic*64 + q*8);
            ok = 1;
        } else {
            int xi = row + dx - 1;
            ok = yok && ((unsigned)xi < 128u);
            int yc = ok ? yi : 0, xc = ok ? xi : 0;
            g = g_xh + (((size_t)b*PLANE + yc*HWD + xc)*CI + cic*64 + q*8);
        }
        cpasync16(soff, g, ok);
    }
}

__device__ __forceinline__ void compute_stage(uint32_t sbase, int wm, int wn,
                                              int lane, float acc[4][4][4]){
    uint32_t aW = sbase;
    uint32_t aX = sbase + 16384;
    #pragma unroll
    for (int ks = 0; ks < 4; ks++){
        uint32_t a[4][4];
        #pragma unroll
        for (int mi = 0; mi < 4; mi++){
            int row = wm*64 + mi*16 + (lane & 15);
            int ch  = ks*2 + (lane >> 4);
            ldm_x4(a[mi][0], a[mi][1], a[mi][2], a[mi][3],
                   aW + row*128 + (((uint32_t)(ch ^ (row & 7))) << 4));
        }
        uint32_t bh[4][2];
        #pragma unroll
        for (int ni = 0; ni < 4; ni++){
            int row = wn*32 + ni*8 + (lane & 7);
            int ch  = ks*2 + ((lane >> 3) & 1);
            uint32_t off = row*128 + (((uint32_t)(ch ^ (row & 7))) << 4);
            ldm_x2(bh[ni][0], bh[ni][1], aX + off);
        }
        #pragma unroll
        for (int mi = 0; mi < 4; mi++)
            #pragma unroll
            for (int ni = 0; ni < 4; ni++)
                mma16816(acc[mi][ni], a[mi], bh[ni]);
    }
}

__global__ __launch_bounds__(256, 2)
void k_conv_mma(){
    extern __shared__ char dsm[];
    uint32_t sb0 = smem_u32(dsm);
    sb0 = (sb0 + 127u) & ~127u;

    int tid = threadIdx.x, lane = tid & 31, wid = tid >> 5;
    int wm = wid & 1, wn = wid >> 1;      // 2(M) x 4(N)
    int y = blockIdx.x, b = blockIdx.y;

    float acc[4][4][4];
    #pragma unroll
    for (int mi = 0; mi < 4; mi++)
        #pragma unroll
        for (int ni = 0; ni < 4; ni++)
            #pragma unroll
            for (int k = 0; k < 4; k++) acc[mi][ni][k] = 0.f;

    fill_stage(sb0, b, y, 0, tid);
    CP_COMMIT();

    for (int it = 0; it < 36; it++){
        int s = it & 1;
        if (it < 35){
            fill_stage(sb0 + ((it + 1) & 1)*STG, b, y, it + 1, tid);
            CP_COMMIT();
            asm volatile("cp.async.wait_group 1;" ::: "memory");
        } else {
            asm volatile("cp.async.wait_group 0;" ::: "memory");
        }
        __syncthreads();
        compute_stage(sb0 + s*STG, wm, wn, lane, acc);
        __syncthreads();
    }

    // epilogue: acc (m=co, n=px) -> g_fuse[b][co][y][px], px-contiguous float2
    int g  = lane >> 2;
    int tq = lane & 3;
    #pragma unroll
    for (int mi = 0; mi < 4; mi++){
        #pragma unroll
        for (int ni = 0; ni < 4; ni++){
            int co = wm*64 + mi*16 + g;
            int px = wn*32 + ni*8 + tq*2;
            size_t o = ((size_t)(b*C + co))*PLANE + (size_t)y*HWD + px;
            float2 v0; v0.x = acc[mi][ni][0]; v0.y = acc[mi][ni][1];
            float2 v1; v1.x = acc[mi][ni][2]; v1.y = acc[mi][ni][3];
            *(float2*)(g_fuse + o)                      = v0;
            *(float2*)(g_fuse + o + (size_t)8*PLANE)    = v1;
        }
    }
}

// ---------------- segment reduction ----------------
// grid (32 tiles of 4 rows, B), block 256, 2 channel-half accumulators.
__global__ void k_seg(const float* __restrict__ feats_d,
                      const int*   __restrict__ label,
                      int which){
    __shared__ float ssum[2][L*C];          // 42 KB
    __shared__ unsigned char slab[512];
    __shared__ int scnt[L];
    int b    = blockIdx.y;
    int tile = blockIdx.x;
    int tid  = threadIdx.x;
    int c = tid & 127, h = tid >> 7;

    for (int i = tid; i < 2*L*C; i += 256) ((float*)ssum)[i] = 0.f;
    if (tid < L) scnt[tid] = 0;
    __syncthreads();

    int y0 = tile * 4;
    const int* lb = label + (size_t)b * 512 * 512;
    for (int p = tid; p < 512; p += 256){
        int y = y0 + (p >> 7);
        int x = p & 127;
        int lv = lb[(y << 2) * 512 + (x << 2)];   // nearest resize: idx*4
        slab[p] = (unsigned char)lv;
        if (which == 0) atomicAdd(&scnt[lv], 1);
    }
    __syncthreads();

    const float* src = (which == 0) ? feats_d : g_fuse;
    const float* f = src + ((size_t)b*C + c) * PLANE + (size_t)y0 * HWD;
    float* sm = ssum[h];
    int pbase = h * 256;                    // half h -> 2 rows (256 px)
    #pragma unroll 4
    for (int i = 0; i < 256; i += 4){
        int p = pbase + i;
        float4 v = *(const float4*)(f + p);
        sm[slab[p+0]*C + c] += v.x;
        sm[slab[p+1]*C + c] += v.y;
        sm[slab[p+2]*C + c] += v.z;
        sm[slab[p+3]*C + c] += v.w;
    }
    __syncthreads();

    float* sums = (which == 0) ? g_sum_d : g_sum_f;
    for (int i = tid; i < L*C; i += 256)
        atomicAdd(&sums[b*L*C + i], ssum[0][i] + ssum[1][i]);
    if (which == 0 && tid < L) atomicAdd(&g_cnt[b*L + tid], scnt[tid]);
}

// ---------------- gate ----------------
__global__ void k_gate(int which,
                       const float* __restrict__ base,
                       const float* __restrict__ w1,
                       const float* __restrict__ w2){
    int b = blockIdx.x;
    int c = threadIdx.x;
    __shared__ float s_s[C];
    __shared__ float s_h[8];
    const float* sums = (which == 0) ? g_sum_d : g_sum_f;

    float sm = 0.f, n2 = 0.f;
    for (int l = 0; l < L; l++){
        int   cnt = g_cnt[b*L + l];
        float m;
        if (cnt > 0) m = sums[(b*L + l)*C + c] / (float)cnt;
        else         m = base[(b*L + l)*C + c];
        sm += m;
        n2 += m * m;
    }
    s_s[c] = sm / fmaxf(sqrtf(n2), 1e-12f);
    __syncthreads();
    if (c < 8){
        float a = 0.f;
        for (int k = 0; k < C; k++) a += s_s[k] * w1[c*C + k];
        s_h[c] = fmaxf(a, 0.f);
    }
    __syncthreads();
    float a = 0.f;
    #pragma unroll
    for (int o = 0; o < 8; o++) a += s_h[o] * w2[c*8 + o];
    float g = sigmoidf(a);
    if (which == 0) g_gd[b*C + c] = g;
    else            g_gf[b*C + c] = g;
}

// ---------------- final gated sum ----------------
__global__ void k_final(const float* __restrict__ dten, float* __restrict__ out){
    size_t i = (size_t)blockIdx.x*256 + threadIdx.x;
    size_t e = i * 4;
    int bc = (int)(e >> 14);
    float gf = g_gf[bc];
    float gd = g_gd[bc];
    float4 f4 = *(const float4*)(g_fuse + e);
    float4 d4 = *(const float4*)(dten + e);
    float4 o;
    o.x = f4.x*gf + d4.x*gd;
    o.y = f4.y*gf + d4.y*gd;
    o.z = f4.z*gf + d4.z*gd;
    o.w = f4.w*gf + d4.w*gd;
    *(float4*)(out + e) = o;
}

// ---------------- launch ----------------
extern "C" void kernel_launch(void* const* d_in, const int* in_sizes, int n_in,
                              void* d_out, int out_size){
    const float* r      = (const float*)d_in[0];
    const float* d      = (const float*)d_in[1];
    const int*   label  = (const int*)  d_in[2];
    const float* conv_w = (const float*)d_in[3];
    const float* f_w1   = (const float*)d_in[4];
    const float* f_w2   = (const float*)d_in[5];
    const float* d_w1   = (const float*)d_in[6];
    const float* d_w2   = (const float*)d_in[7];
    const float* base_f = (const float*)d_in[8];
    const float* base_d = (const float*)d_in[9];
    float* out = (float*)d_out;

    const int prepx_smem = CI*XP_PITCH*2;
    const int conv_smem  = 2*STG + 128;
    cudaFuncSetAttribute(kprep_x, cudaFuncAttributeMaxDynamicSharedMemorySize, prepx_smem);
    cudaFuncSetAttribute(k_conv_mma, cudaFuncAttributeMaxDynamicSharedMemorySize, conv_smem);

    k_zero<<<(B*L*C + 255)/256, 256>>>();

    dim3 wgrid(9, C);
    kprep_w<<<wgrid, CI>>>(conv_w);

    dim3 xgrid(HWD, B);
    kprep_x<<<xgrid, 256, prepx_smem>>>(r, d);

    dim3 segGrid(32, B);
    k_seg<<<segGrid, 256>>>(d, label, 0);
    k_gate<<<B, 128>>>(0, base_d, d_w1, d_w2);

    dim3 convGrid(HWD, B);
    k_conv_mma<<<convGrid, 256, conv_smem>>>();

    k_seg<<<segGrid, 256>>>(d, label, 1);
    k_gate<<<B, 128>>>(1, base_f, f_w1, f_w2);

    k_final<<<(B*C*PLANE/4 + 255)/256, 256>>>(d, out);
}